// round 6
// baseline (speedup 1.0000x reference)
#include <cuda_runtime.h>
#include <cuda_bf16.h>
#include <cstdint>

// CrossAttention, bf16 mma.sync:
//   out = softmax((x Wq)(ctx Wk)^T * DIM^-0.5) (ctx Wv) + x
// x[4,4096,512] ctx[4,4096,768] Wq[512,512] Wk/Wv[768,512]
// GEMM: CTA tile 256x128, BK=64, 3-stage cp.async, 8 warps (2x4), warp 128x32.
// S stored bf16 (scale folded), softmax in-place bf16.

#define BATCH 4
#define SEQ   4096
#define DIM   512
#define CTXD  768

typedef __nv_bfloat16 bf16;

// ---------------- scratch (__device__ globals; allocation-free rule) --------
__device__ bf16  g_Xb [(size_t)BATCH * SEQ * DIM];
__device__ bf16  g_Cb [(size_t)BATCH * SEQ * CTXD];
__device__ bf16  g_WqT[(size_t)DIM * DIM];
__device__ bf16  g_WkT[(size_t)DIM * CTXD];
__device__ bf16  g_WvT[(size_t)DIM * CTXD];
__device__ bf16  g_Qb [(size_t)BATCH * SEQ * DIM];
__device__ bf16  g_Kb [(size_t)BATCH * SEQ * DIM];
__device__ bf16  g_Vb [(size_t)BATCH * SEQ * DIM];
__device__ bf16  g_VT [(size_t)BATCH * DIM * SEQ];
__device__ bf16  g_P  [(size_t)BATCH * SEQ * SEQ];    // S then softmax in-place

// ---------------- PTX helpers ------------------------------------------------
__device__ __forceinline__ uint32_t smem_u32(const void* p) {
    uint32_t a;
    asm("{ .reg .u64 t; cvta.to.shared.u64 t, %1; cvt.u32.u64 %0, t; }"
        : "=r"(a) : "l"(p));
    return a;
}
#define CP_ASYNC16(dst, src) \
    asm volatile("cp.async.cg.shared.global [%0], [%1], 16;" :: "r"(dst), "l"(src))
#define CP_COMMIT() asm volatile("cp.async.commit_group;" ::: "memory")
#define CP_WAIT(n)  asm volatile("cp.async.wait_group %0;" :: "n"(n) : "memory")

#define LDSM4(r0, r1, r2, r3, addr) \
    asm volatile("ldmatrix.sync.aligned.m8n8.x4.shared.b16 {%0,%1,%2,%3}, [%4];" \
        : "=r"(r0), "=r"(r1), "=r"(r2), "=r"(r3) : "r"(addr))

#define MMA16816(d, a, b) \
    asm volatile("mma.sync.aligned.m16n8k16.row.col.f32.bf16.bf16.f32 " \
        "{%0,%1,%2,%3}, {%4,%5,%6,%7}, {%8,%9}, {%0,%1,%2,%3};" \
        : "+f"((d)[0]), "+f"((d)[1]), "+f"((d)[2]), "+f"((d)[3]) \
        : "r"((a)[0]), "r"((a)[1]), "r"((a)[2]), "r"((a)[3]), \
          "r"((b)[0]), "r"((b)[1]))

__device__ __forceinline__ uint32_t pk2(float lo, float hi) {
    __nv_bfloat162 h = __floats2bfloat162_rn(lo, hi);
    return *reinterpret_cast<uint32_t*>(&h);
}

// ---------------- bf16 mma GEMM: D = A(M,K) * B(N,K)^T ----------------------
// CTA 256x128, BK=64 (SW128 rows), 3 stages. MODE: 0 = bf16 out * alpha,
// 2 = f32 out + residual.
#define STAGES 3
#define A_BYTES 32768                 // 256 x 64 bf16
#define B_BYTES 16384                 // 128 x 64 bf16
#define STAGE_BYTES (A_BYTES + B_BYTES)
#define GEMM_SMEM (STAGES * STAGE_BYTES + 128)

__device__ __forceinline__ void tile_async_A(const bf16* g, int ld, uint32_t stg, int tid) {
#pragma unroll
    for (int t = 0; t < 8; t++) {
        const int f   = tid + t * 256;
        const int row = f >> 3;
        const int seg = f & 7;
        CP_ASYNC16(stg + row * 128 + ((seg ^ (row & 7)) << 4),
                   (const char*)g + (long)row * ld * 2 + seg * 16);
    }
}
__device__ __forceinline__ void tile_async_B(const bf16* g, int ld, uint32_t stg, int tid) {
#pragma unroll
    for (int t = 0; t < 4; t++) {
        const int f   = tid + t * 256;
        const int row = f >> 3;
        const int seg = f & 7;
        CP_ASYNC16(stg + row * 128 + ((seg ^ (row & 7)) << 4),
                   (const char*)g + (long)row * ld * 2 + seg * 16);
    }
}

template <int MODE>
__global__ __launch_bounds__(256)
void gemm_mma(const bf16* __restrict__ A, const bf16* __restrict__ B,
              void* __restrict__ Cv, const float* __restrict__ R,
              int Ncols, int Kd, long sA, long sB, long sC, float alpha)
{
    extern __shared__ char smraw[];
    const uint32_t smbase = (smem_u32(smraw) + 127u) & ~127u;

    const int tid  = threadIdx.x;
    const int lane = tid & 31;
    const int wid  = tid >> 5;
    const int wm   = wid >> 2;                 // 0..1  (128 rows each)
    const int wn   = wid & 3;                  // 0..3  (32 cols each)
    const int bz   = blockIdx.z;
    const long bm  = (long)blockIdx.y * 256;
    const long bn  = (long)blockIdx.x * 128;

    A += bz * sA + bm * Kd;
    B += bz * sB + bn * Kd;

    const int g  = lane >> 3, lr = lane & 7;
    const int arow0 = wm * 128 + (g & 1) * 8 + lr;
    const int aseg0 = g >> 1;
    const int axor  = arow0 & 7;
    const int brow0 = wn * 32 + (g >> 1) * 8 + lr;
    const int bseg0 = g & 1;
    const int bxor  = brow0 & 7;

    float acc[8][4][4];
#pragma unroll
    for (int i = 0; i < 8; i++)
#pragma unroll
        for (int j = 0; j < 4; j++)
#pragma unroll
            for (int q = 0; q < 4; q++) acc[i][j][q] = 0.0f;

    const int NC = Kd >> 6;

#pragma unroll
    for (int c = 0; c < 2; c++) {
        const uint32_t stg = smbase + c * STAGE_BYTES;
        tile_async_A(A + c * 64, Kd, stg, tid);
        tile_async_B(B + c * 64, Kd, stg + A_BYTES, tid);
        CP_COMMIT();
    }

    for (int c = 0; c < NC; c++) {
        if (c == NC - 1) { CP_WAIT(0); } else { CP_WAIT(1); }
        __syncthreads();

        if (c + 2 < NC) {
            const uint32_t stg = smbase + ((c + 2) % STAGES) * STAGE_BYTES;
            tile_async_A(A + (c + 2) * 64, Kd, stg, tid);
            tile_async_B(B + (c + 2) * 64, Kd, stg + A_BYTES, tid);
            CP_COMMIT();
        }

        const uint32_t sa = smbase + (c % STAGES) * STAGE_BYTES;
        const uint32_t sb = sa + A_BYTES;
#pragma unroll
        for (int ks = 0; ks < 4; ks++) {
            uint32_t af[8][4];
#pragma unroll
            for (int i = 0; i < 8; i++)
                LDSM4(af[i][0], af[i][1], af[i][2], af[i][3],
                      sa + (arow0 + i * 16) * 128 + ((((ks << 1) + aseg0) ^ axor) << 4));
            uint32_t bfr[4][2];
#pragma unroll
            for (int jp = 0; jp < 2; jp++) {
                uint32_t r0, r1, r2, r3;
                LDSM4(r0, r1, r2, r3,
                      sb + (brow0 + jp * 16) * 128 + ((((ks << 1) + bseg0) ^ bxor) << 4));
                bfr[2 * jp][0] = r0; bfr[2 * jp][1] = r1;
                bfr[2 * jp + 1][0] = r2; bfr[2 * jp + 1][1] = r3;
            }
#pragma unroll
            for (int i = 0; i < 8; i++)
#pragma unroll
                for (int j = 0; j < 4; j++)
                    MMA16816(acc[i][j], af[i], bfr[j]);
        }
    }

    // ---------------- epilogue ----------------
    const int r  = lane >> 2;
    const int c2 = (lane & 3) * 2;
    const long rowBase = bm + wm * 128;
    const int  colBase = bn + wn * 32;

#pragma unroll
    for (int i = 0; i < 8; i++) {
#pragma unroll
        for (int j = 0; j < 4; j++) {
            const long row0 = rowBase + i * 16 + r;
            const int  col  = colBase + j * 8 + c2;
            const long o0 = (row0)     * (long)Ncols + col + bz * sC;
            const long o1 = (row0 + 8) * (long)Ncols + col + bz * sC;
            if (MODE == 0) {
                *(uint32_t*)((bf16*)Cv + o0) = pk2(acc[i][j][0] * alpha, acc[i][j][1] * alpha);
                *(uint32_t*)((bf16*)Cv + o1) = pk2(acc[i][j][2] * alpha, acc[i][j][3] * alpha);
            } else {
                const float2 r0 = *(const float2*)(R + o0);
                const float2 r1 = *(const float2*)(R + o1);
                *(float2*)((float*)Cv + o0) =
                    make_float2(acc[i][j][0] + r0.x, acc[i][j][1] + r0.y);
                *(float2*)((float*)Cv + o1) =
                    make_float2(acc[i][j][2] + r1.x, acc[i][j][3] + r1.y);
            }
        }
    }
}

// ---------------- helper kernels -------------------------------------------
__global__ __launch_bounds__(256)
void cvt_bf16(const float* __restrict__ in, bf16* __restrict__ out) {
    const long i = (long)blockIdx.x * 256 + threadIdx.x;
    const float4* p = (const float4*)in + i * 2;
    const float4 a = p[0], b = p[1];
    ((uint4*)out)[i] = make_uint4(pk2(a.x, a.y), pk2(a.z, a.w),
                                  pk2(b.x, b.y), pk2(b.z, b.w));
}

__global__ __launch_bounds__(256)
void wtransb(const float* __restrict__ W, bf16* __restrict__ WT, int Kin, int Nout) {
    __shared__ float t[32][33];
    const int n0 = blockIdx.x * 32, k0 = blockIdx.y * 32;
    const int tx = threadIdx.x & 31, ty = threadIdx.x >> 5;
#pragma unroll
    for (int i = 0; i < 4; i++)
        t[ty + 8 * i][tx] = W[(long)(k0 + ty + 8 * i) * Nout + n0 + tx];
    __syncthreads();
#pragma unroll
    for (int i = 0; i < 4; i++)
        WT[(long)(n0 + ty + 8 * i) * Kin + k0 + tx] = __float2bfloat16(t[tx][ty + 8 * i]);
}

__global__ __launch_bounds__(256)
void vtransb(const bf16* __restrict__ V, bf16* __restrict__ VT) {
    __shared__ bf16 t[32][33];
    const long boff = (long)blockIdx.z * SEQ * DIM;
    const int d0 = blockIdx.x * 32, m0 = blockIdx.y * 32;
    const int tx = threadIdx.x & 31, ty = threadIdx.x >> 5;
#pragma unroll
    for (int i = 0; i < 4; i++)
        t[ty + 8 * i][tx] = V[boff + (long)(m0 + ty + 8 * i) * DIM + d0 + tx];
    __syncthreads();
#pragma unroll
    for (int i = 0; i < 4; i++)
        VT[boff + (long)(d0 + ty + 8 * i) * SEQ + m0 + tx] = t[tx][ty + 8 * i];
}

// in-place row softmax over bf16 [rows, 4096]
__global__ __launch_bounds__(256)
void softmax_bf16(bf16* __restrict__ P) {
    const long row = blockIdx.x;
    const int tid = threadIdx.x;
    uint4* rp = (uint4*)(P + row * SEQ) + tid * 2;
    const uint4 u0 = rp[0], u1 = rp[1];
    float v[16];
    {
        const uint32_t w[8] = {u0.x, u0.y, u0.z, u0.w, u1.x, u1.y, u1.z, u1.w};
#pragma unroll
        for (int q = 0; q < 8; q++) {
            const __nv_bfloat162 h = *reinterpret_cast<const __nv_bfloat162*>(&w[q]);
            const float2 f = __bfloat1622float2(h);
            v[2 * q] = f.x; v[2 * q + 1] = f.y;
        }
    }
    float lmax = -1e30f;
#pragma unroll
    for (int t = 0; t < 16; t++) lmax = fmaxf(lmax, v[t]);
#pragma unroll
    for (int o = 16; o > 0; o >>= 1)
        lmax = fmaxf(lmax, __shfl_xor_sync(0xFFFFFFFFu, lmax, o));
    __shared__ float rmax[8], rsum[8];
    if ((tid & 31) == 0) rmax[tid >> 5] = lmax;
    __syncthreads();
    float bmax = rmax[0];
#pragma unroll
    for (int w = 1; w < 8; w++) bmax = fmaxf(bmax, rmax[w]);
    float lsum = 0.0f;
#pragma unroll
    for (int t = 0; t < 16; t++) { v[t] = __expf(v[t] - bmax); lsum += v[t]; }
#pragma unroll
    for (int o = 16; o > 0; o >>= 1)
        lsum += __shfl_xor_sync(0xFFFFFFFFu, lsum, o);
    if ((tid & 31) == 0) rsum[tid >> 5] = lsum;
    __syncthreads();
    float bsum = 0.0f;
#pragma unroll
    for (int w = 0; w < 8; w++) bsum += rsum[w];
    const float inv = 1.0f / bsum;
#pragma unroll
    for (int q = 0; q < 2; q++) {
        uint4 o;
        o.x = pk2(v[8 * q + 0] * inv, v[8 * q + 1] * inv);
        o.y = pk2(v[8 * q + 2] * inv, v[8 * q + 3] * inv);
        o.z = pk2(v[8 * q + 4] * inv, v[8 * q + 5] * inv);
        o.w = pk2(v[8 * q + 6] * inv, v[8 * q + 7] * inv);
        rp[q] = o;
    }
}

// ---------------- launcher ---------------------------------------------------
extern "C" void kernel_launch(void* const* d_in, const int* in_sizes, int n_in,
                              void* d_out, int out_size)
{
    const float* x   = (const float*)d_in[0];
    const float* ctx = (const float*)d_in[1];
    const float* Wq  = (const float*)d_in[2];
    const float* Wk  = (const float*)d_in[3];
    const float* Wv  = (const float*)d_in[4];
    float* out = (float*)d_out;

    bf16 *Xb, *Cb, *WqT, *WkT, *WvT, *Qb, *Kb, *Vb, *VT, *P;
    cudaGetSymbolAddress((void**)&Xb,  g_Xb);
    cudaGetSymbolAddress((void**)&Cb,  g_Cb);
    cudaGetSymbolAddress((void**)&WqT, g_WqT);
    cudaGetSymbolAddress((void**)&WkT, g_WkT);
    cudaGetSymbolAddress((void**)&WvT, g_WvT);
    cudaGetSymbolAddress((void**)&Qb,  g_Qb);
    cudaGetSymbolAddress((void**)&Kb,  g_Kb);
    cudaGetSymbolAddress((void**)&Vb,  g_Vb);
    cudaGetSymbolAddress((void**)&VT,  g_VT);
    cudaGetSymbolAddress((void**)&P,   g_P);

    cudaFuncSetAttribute(gemm_mma<0>, cudaFuncAttributeMaxDynamicSharedMemorySize, GEMM_SMEM);
    cudaFuncSetAttribute(gemm_mma<2>, cudaFuncAttributeMaxDynamicSharedMemorySize, GEMM_SMEM);

    const float scale = 0.044194173824159216f;  // 512^-0.5

    cvt_bf16<<<(BATCH * SEQ * DIM)  / (256 * 8), 256>>>(x,   Xb);
    cvt_bf16<<<(BATCH * SEQ * CTXD) / (256 * 8), 256>>>(ctx, Cb);

    wtransb<<<dim3(DIM / 32, DIM  / 32), 256>>>(Wq, WqT, DIM,  DIM);
    wtransb<<<dim3(DIM / 32, CTXD / 32), 256>>>(Wk, WkT, CTXD, DIM);
    wtransb<<<dim3(DIM / 32, CTXD / 32), 256>>>(Wv, WvT, CTXD, DIM);

    // projections (batch folded: 16384 rows, 256-row tiles)
    gemm_mma<0><<<dim3(DIM / 128, (BATCH * SEQ) / 256, 1), 256, GEMM_SMEM>>>(
        Xb, WqT, Qb, nullptr, DIM, DIM, 0, 0, 0, 1.0f);
    gemm_mma<0><<<dim3(DIM / 128, (BATCH * SEQ) / 256, 1), 256, GEMM_SMEM>>>(
        Cb, WkT, Kb, nullptr, DIM, CTXD, 0, 0, 0, 1.0f);
    gemm_mma<0><<<dim3(DIM / 128, (BATCH * SEQ) / 256, 1), 256, GEMM_SMEM>>>(
        Cb, WvT, Vb, nullptr, DIM, CTXD, 0, 0, 0, 1.0f);

    vtransb<<<dim3(DIM / 32, SEQ / 32, BATCH), 256>>>(Vb, VT);

    // S = scale * Q K^T  -> bf16 into P
    gemm_mma<0><<<dim3(SEQ / 128, SEQ / 256, BATCH), 256, GEMM_SMEM>>>(
        Qb, Kb, P, nullptr, SEQ, DIM,
        (long)SEQ * DIM, (long)SEQ * DIM, (long)SEQ * SEQ, scale);

    // softmax in place
    softmax_bf16<<<BATCH * SEQ, 256>>>(P);

    // out = P V + x
    gemm_mma<2><<<dim3(DIM / 128, SEQ / 256, BATCH), 256, GEMM_SMEM>>>(
        P, VT, out, x, DIM, SEQ,
        (long)SEQ * SEQ, (long)DIM * SEQ, (long)SEQ * DIM, 1.0f);
}